// round 9
// baseline (speedup 1.0000x reference)
#include <cuda_runtime.h>

#define H 512
#define W 512
#define HW (H * W)
#define BN_EPS 1e-5f
#define RING (4 * W - 4)          // 2044 ring pixels per batch
#define BPX 14                    // border pixels per border block (14*9=126 thr)
#define NBY_MAIN 16               // 512 / 32 rows per main block
#define NBY_EXTRA 10              // 160 border blocks per batch (need 146)

typedef unsigned long long u64;

// Precomputed effective weights (written by prep_kernel each launch).
__device__ float g_Weff[675];   // [(c*5+u)*5+v]*9+k
__device__ float g_W0[243];     // [(j*3+u)*3+v]*9+k
__device__ float g_Shift[9];

// ---------------- packed f32x2 helpers ----------------
__device__ __forceinline__ u64 pk(float a, float b) {
    u64 d;
    asm("mov.b64 %0, {%1, %2};" : "=l"(d) : "f"(a), "f"(b));
    return d;
}
__device__ __forceinline__ void upk(u64 d, float& a, float& b) {
    asm("mov.b64 {%0, %1}, %2;" : "=f"(a), "=f"(b) : "l"(d));
}
__device__ __forceinline__ void fma2(u64& c, u64 a, u64 b) {
    asm("fma.rn.f32x2 %0, %1, %2, %0;" : "+l"(c) : "l"(a), "l"(b));
}
__device__ __forceinline__ u64 add2(u64 a, u64 b) {
    u64 d;
    asm("add.rn.f32x2 %0, %1, %2;" : "=l"(d) : "l"(a), "l"(b));
    return d;
}

// ---------------------------------------------------------------------------
// Kernel 1: prep — one weight per thread.
// ---------------------------------------------------------------------------
__global__ void prep_kernel(const float* __restrict__ cw,
                            const float* __restrict__ gam,
                            const float* __restrict__ bet,
                            const float* __restrict__ mu,
                            const float* __restrict__ var) {
    int tid = blockIdx.x * blockDim.x + threadIdx.x;
    if (tid < 675) {
        int k = tid % 9;
        int rest = tid / 9;
        int v = rest % 5; rest /= 5;
        int u = rest % 5;
        int c = rest / 5;
        float s = gam[k] * rsqrtf(var[k] + BN_EPS);
        float sum = 0.f;
#pragma unroll
        for (int ti = 0; ti < 3; ti++) {
            int di = u - ti;
            if (di < 0 || di > 2) continue;
#pragma unroll
            for (int tj = 0; tj < 3; tj++) {
                int dj = v - tj;
                if (dj < 0 || dj > 2) continue;
                int t = ti * 3 + tj;
                if (c == 0 && t >= 4 && t <= 6) continue;   // replaced rows
                sum += cw[((k * 27 + c * 9 + t) * 3 + di) * 3 + dj];
            }
        }
        g_Weff[tid] = s * sum;
    } else if (tid < 675 + 243) {
        int i = tid - 675;
        int k = i % 9;
        int rest = i / 9;
        int v = rest % 3; rest /= 3;
        int u = rest % 3;
        int j = rest / 3;
        float s = gam[k] * rsqrtf(var[k] + BN_EPS);
        g_W0[i] = s * cw[((k * 27 + 4 + j) * 3 + u) * 3 + v];
    } else if (tid < 675 + 243 + 9) {
        int k = tid - 918;
        float s = gam[k] * rsqrtf(var[k] + BN_EPS);
        g_Shift[k] = bet[k] - mu[k] * s;
    }
}

// ---------------------------------------------------------------------------
// Row loaders over window [w0-2, w0+5].
// ---------------------------------------------------------------------------
__device__ __forceinline__ void load_row8_fast(const float* __restrict__ p,
                                               float v[8], u64 dup[8]) {
    u64 a = *(const u64*)(p - 2);
    float4 m = *(const float4*)(p);
    u64 c = *(const u64*)(p + 4);
    upk(a, v[0], v[1]);
    v[2] = m.x; v[3] = m.y; v[4] = m.z; v[5] = m.w;
    upk(c, v[6], v[7]);
#pragma unroll
    for (int i = 0; i < 8; i++) dup[i] = pk(v[i], v[i]);
}

__device__ __forceinline__ void load_row8_guard(const float* __restrict__ rowp, int w0,
                                                bool rowok, bool colsafe,
                                                float v[8], u64 dup[8]) {
    if (rowok && colsafe) {
        load_row8_fast(rowp + w0, v, dup);
        return;
    }
    if (rowok) {
#pragma unroll
        for (int i = 0; i < 8; i++) {
            int ww = w0 - 2 + i;
            v[i] = (ww >= 0 && ww < W) ? rowp[ww] : 0.f;
        }
    } else {
#pragma unroll
        for (int i = 0; i < 8; i++) v[i] = 0.f;
    }
#pragma unroll
    for (int i = 0; i < 8; i++) dup[i] = pk(v[i], v[i]);
}

// Apply one tap's 9 weights to 4 pixels starting at `base`.
__device__ __forceinline__ void apply_tap(const float* __restrict__ wt,
                                          const float v[8], const u64 dup[8], int base,
                                          u64 accp[4][4], float acc8[4]) {
    ulonglong2 qa = *(const ulonglong2*)(wt);
    ulonglong2 qb = *(const ulonglong2*)(wt + 4);
    float w8 = wt[8];
#pragma unroll
    for (int p = 0; p < 4; p++) {
        u64 d = dup[base + p];
        fma2(accp[p][0], qa.x, d);
        fma2(accp[p][1], qa.y, d);
        fma2(accp[p][2], qb.x, d);
        fma2(accp[p][3], qb.y, d);
        acc8[p] = fmaf(w8, v[base + p], acc8[p]);
    }
}

// 5 taps of one 5x5 weight row.
__device__ __forceinline__ void apply5(const float* __restrict__ wrow,
                                       const float v[8], const u64 dup[8],
                                       u64 accp[4][4], float acc8[4]) {
#pragma unroll
    for (int tv = 0; tv < 5; tv++)
        apply_tap(wrow + tv * 12, v, dup, tv, accp, acc8);
}
// 3 taps of one 3x3 weight row (data offset +1).
__device__ __forceinline__ void apply3(const float* __restrict__ wrow,
                                       const float v[8], const u64 dup[8],
                                       u64 accp[4][4], float acc8[4]) {
#pragma unroll
    for (int tv = 0; tv < 3; tv++)
        apply_tap(wrow + tv * 12, v, dup, 1 + tv, accp, acc8);
}

// ---------------------------------------------------------------------------
// Kernel 2: fused main + border.
//   blockIdx.y <  NBY_MAIN : main tile block (8x16 thr, 4x2 px/thread, 32x32 tile)
//   blockIdx.y >= NBY_MAIN : border block (14 px x 9 didx) for the 1-px ring
// ---------------------------------------------------------------------------
__global__ __launch_bounds__(128, 4) void cspn_main(
        const float* __restrict__ ker,
        const float* __restrict__ in,
        const float* __restrict__ in0,
        const float* __restrict__ cw,
        const float* __restrict__ gam,
        const float* __restrict__ bet,
        const float* __restrict__ mu,
        const float* __restrict__ var,
        float* __restrict__ out) {
    __shared__ __align__(16) char smem_raw[13312];

    const int b = blockIdx.z;
    const int tid = threadIdx.y * 8 + threadIdx.x;

    if (blockIdx.y >= NBY_MAIN) {
        // ================= border path =================
        float* sw   = (float*)smem_raw;                 // [2187]
        float* pacc = (float*)(smem_raw + 8752);        // [BPX][9][9]

        for (int i = tid; i < 2187; i += 128) sw[i] = cw[i];
        __syncthreads();

        const int bidx = (blockIdx.y - NBY_MAIN) * 16 + blockIdx.x;
        const int base = bidx * BPX;

        const int px   = tid / 9;
        const int didx = tid % 9;
        const int pos  = base + px;
        const bool active = (tid < 126) && (pos < RING);

        float acc[9];
#pragma unroll
        for (int k = 0; k < 9; k++) acc[k] = 0.f;

        if (active) {
            int h, w;
            if (pos < W)          { h = 0;     w = pos; }
            else if (pos < 2 * W) { h = H - 1; w = pos - W; }
            else {
                int p2 = pos - 2 * W;
                h = 1 + (p2 >> 1);
                w = (p2 & 1) ? (W - 1) : 0;
            }
            const float* inb  = in  + (size_t)b * 3 * HW;
            const float* in0b = in0 + (size_t)b * 3 * HW;
            const int dy = didx / 3 - 1, dx = didx % 3 - 1;
            const int qy = h + dy, qx = w + dx;
            const bool qok = (qy >= 0 && qy < H && qx >= 0 && qx < W);
#pragma unroll
            for (int ch = 0; ch < 27; ch++) {
                float val;
                if (ch >= 4 && ch <= 6) {
                    val = qok ? in0b[(ch - 4) * HW + qy * W + qx] : 0.f;
                } else {
                    int c = ch / 9, t = ch % 9;
                    int py = qy + t / 3 - 1, qx2 = qx + t % 3 - 1;
                    bool pok = qok && (py >= 0 && py < H && qx2 >= 0 && qx2 < W);
                    val = pok ? inb[c * HW + py * W + qx2] : 0.f;
                }
#pragma unroll
                for (int k = 0; k < 9; k++)
                    acc[k] = fmaf(sw[(k * 27 + ch) * 9 + didx], val, acc[k]);
            }
        }
        if (tid < 126) {
#pragma unroll
            for (int k = 0; k < 9; k++) pacc[(px * 9 + didx) * 9 + k] = acc[k];
        }
        __syncthreads();

        if (tid < BPX) {
            int pos2 = base + tid;
            if (pos2 < RING) {
                int hh, ww;
                if (pos2 < W)          { hh = 0;     ww = pos2; }
                else if (pos2 < 2 * W) { hh = H - 1; ww = pos2 - W; }
                else {
                    int p2 = pos2 - 2 * W;
                    hh = 1 + (p2 >> 1);
                    ww = (p2 & 1) ? (W - 1) : 0;
                }
                float r = 0.f;
#pragma unroll
                for (int k = 0; k < 9; k++) {
                    float s = 0.f;
#pragma unroll
                    for (int d = 0; d < 9; d++) s += pacc[(tid * 9 + d) * 9 + k];
                    float sc = gam[k] * rsqrtf(var[k] + BN_EPS);
                    float sh = bet[k] - mu[k] * sc;
                    r = fmaf(ker[((size_t)b * 9 + k) * HW + hh * W + ww],
                             fmaf(sc, s, sh), r);
                }
                out[(size_t)b * HW + hh * W + ww] = r;
            }
        }
        return;
    }

    // ================= main path: 2 output rows per thread =================
    float* sW5 = (float*)smem_raw;                   // [75*12]
    float* s03 = (float*)(smem_raw + 3600);          // [27*12]
    u64*  sSp  = (u64*)(smem_raw + 4896);            // [4]
    float* sS8 = (float*)(smem_raw + 4928);

    for (int i = tid; i < 75 * 12; i += 128) {
        int t5 = i / 12, k = i % 12;
        sW5[i] = (k < 9) ? g_Weff[t5 * 9 + k] : 0.f;
    }
    for (int i = tid; i < 27 * 12; i += 128) {
        int t3 = i / 12, k = i % 12;
        s03[i] = (k < 9) ? g_W0[t3 * 9 + k] : 0.f;
    }
    if (tid < 4) sSp[tid] = pk(g_Shift[2 * tid], g_Shift[2 * tid + 1]);
    if (tid == 4) *sS8 = g_Shift[8];
    __syncthreads();

    const int h0 = blockIdx.y * 32 + threadIdx.y * 2;   // rows h0, h0+1
    const int w0 = blockIdx.x * 32 + threadIdx.x * 4;

    u64 accA[4][4], accB[4][4];
    float a8A[4], a8B[4];
#pragma unroll
    for (int p = 0; p < 4; p++) {
        a8A[p] = 0.f; a8B[p] = 0.f;
#pragma unroll
        for (int j = 0; j < 4; j++) { accA[p][j] = 0ull; accB[p][j] = 0ull; }
    }

    const float* inb  = in  + (size_t)b * 3 * HW;
    const float* in0b = in0 + (size_t)b * 3 * HW;

    const bool fast = (blockIdx.x >= 1) && (blockIdx.x <= (W / 32) - 2) &&
                      (blockIdx.y >= 1) && (blockIdx.y <= NBY_MAIN - 2);

    if (fast) {
        // 5x5 on input: 6 shared rows i=0..5 (r = h0-2+i)
        const float* base5 = inb + (h0 - 2) * W + w0;
#pragma unroll
        for (int c = 0; c < 3; c++) {
#pragma unroll
            for (int i = 0; i < 6; i++) {
                float v[8]; u64 dup[8];
                load_row8_fast(base5 + c * HW + i * W, v, dup);
                if (i < 5) apply5(&sW5[(c * 5 + i) * 60], v, dup, accA, a8A);
                if (i >= 1) apply5(&sW5[(c * 5 + i - 1) * 60], v, dup, accB, a8B);
            }
        }
        // 3x3 on input0: 4 shared rows i=0..3 (r = h0-1+i)
        const float* base3 = in0b + (h0 - 1) * W + w0;
#pragma unroll
        for (int j3 = 0; j3 < 3; j3++) {
#pragma unroll
            for (int i = 0; i < 4; i++) {
                float v[8]; u64 dup[8];
                load_row8_fast(base3 + j3 * HW + i * W, v, dup);
                if (i < 3) apply3(&s03[(j3 * 3 + i) * 36], v, dup, accA, a8A);
                if (i >= 1) apply3(&s03[(j3 * 3 + i - 1) * 36], v, dup, accB, a8B);
            }
        }
    } else {
        const bool colsafe = (w0 >= 2) && (w0 + 6 <= W);
#pragma unroll 1
        for (int c = 0; c < 3; c++) {
            const float* inc = inb + c * HW;
#pragma unroll
            for (int i = 0; i < 6; i++) {
                int r = h0 - 2 + i;
                float v[8]; u64 dup[8];
                load_row8_guard(inc + r * W, w0, (r >= 0 && r < H), colsafe, v, dup);
                if (i < 5) apply5(&sW5[(c * 5 + i) * 60], v, dup, accA, a8A);
                if (i >= 1) apply5(&sW5[(c * 5 + i - 1) * 60], v, dup, accB, a8B);
            }
        }
#pragma unroll 1
        for (int j3 = 0; j3 < 3; j3++) {
            const float* inc = in0b + j3 * HW;
#pragma unroll
            for (int i = 0; i < 4; i++) {
                int r = h0 - 1 + i;
                float v[8]; u64 dup[8];
                load_row8_guard(inc + r * W, w0, (r >= 0 && r < H), colsafe, v, dup);
                if (i < 3) apply3(&s03[(j3 * 3 + i) * 36], v, dup, accA, a8A);
                if (i >= 1) apply3(&s03[(j3 * 3 + i - 1) * 36], v, dup, accB, a8B);
            }
        }
    }

    // ---- epilogue per row-group ----
#pragma unroll
    for (int g = 0; g < 2; g++) {
        const int h = h0 + g;
        u64 (*accp)[4] = g ? accB : accA;
        float* a8 = g ? a8B : a8A;

        const float* kp = ker + (size_t)b * 9 * HW + h * W + w0;
        u64 rp[4] = {0ull, 0ull, 0ull, 0ull};
#pragma unroll
        for (int j = 0; j < 4; j++) {
            const float4 ka = *(const float4*)(kp + (2 * j) * HW);
            const float4 kb = *(const float4*)(kp + (2 * j + 1) * HW);
            u64 sh2 = sSp[j];
            fma2(rp[0], pk(ka.x, kb.x), add2(accp[0][j], sh2));
            fma2(rp[1], pk(ka.y, kb.y), add2(accp[1][j], sh2));
            fma2(rp[2], pk(ka.z, kb.z), add2(accp[2][j], sh2));
            fma2(rp[3], pk(ka.w, kb.w), add2(accp[3][j], sh2));
        }
        float res[4];
        {
            const float4 k8 = *(const float4*)(kp + 8 * HW);
            float sh8 = *sS8;
            float lo, hi;
            upk(rp[0], lo, hi); res[0] = lo + hi + k8.x * (a8[0] + sh8);
            upk(rp[1], lo, hi); res[1] = lo + hi + k8.y * (a8[1] + sh8);
            upk(rp[2], lo, hi); res[2] = lo + hi + k8.z * (a8[2] + sh8);
            upk(rp[3], lo, hi); res[3] = lo + hi + k8.w * (a8[3] + sh8);
        }
        if (h >= 1 && h <= H - 2) {
            float* op = out + (size_t)b * HW + h * W + w0;
            if (w0 == 0)          { op[1] = res[1]; op[2] = res[2]; op[3] = res[3]; }
            else if (w0 == W - 4) { op[0] = res[0]; op[1] = res[1]; op[2] = res[2]; }
            else                  { *(float4*)op = make_float4(res[0], res[1], res[2], res[3]); }
        }
    }
}

// ---------------------------------------------------------------------------
extern "C" void kernel_launch(void* const* d_in, const int* in_sizes, int n_in,
                              void* d_out, int out_size) {
    const float* ker = (const float*)d_in[0];
    const float* in  = (const float*)d_in[1];
    const float* in0 = (const float*)d_in[2];
    const float* cw  = (const float*)d_in[3];
    const float* gam = (const float*)d_in[4];
    const float* bet = (const float*)d_in[5];
    const float* mu  = (const float*)d_in[6];
    const float* var = (const float*)d_in[7];
    float* out = (float*)d_out;

    int bs = in_sizes[0] / (9 * HW);   // batch from kernel tensor size

    prep_kernel<<<8, 128>>>(cw, gam, bet, mu, var);

    dim3 blk(8, 16);
    dim3 grd(W / 32, NBY_MAIN + NBY_EXTRA, bs);
    cspn_main<<<grd, blk>>>(ker, in, in0, cw, gam, bet, mu, var, out);
}

// round 10
// speedup vs baseline: 1.2139x; 1.2139x over previous
#include <cuda_runtime.h>

#define H 512
#define W 512
#define HW (H * W)
#define BN_EPS 1e-5f
#define RING (4 * W - 4)          // 2044 ring pixels per batch
#define BPX 14                    // border pixels per border block (14*9=126 thr)
#define NBY_MAIN 32               // 512 / 16 rows per main block
#define NBY_EXTRA 10              // 160 border blocks per batch (need 146)

typedef unsigned long long u64;

// Precomputed effective weights (written by prep_kernel each launch).
__device__ float g_Weff[675];   // [(c*5+u)*5+v]*9+k
__device__ float g_W0[243];     // [(j*3+u)*3+v]*9+k
__device__ float g_Shift[9];

// ---------------- packed f32x2 helpers ----------------
__device__ __forceinline__ u64 pk(float a, float b) {
    u64 d;
    asm("mov.b64 %0, {%1, %2};" : "=l"(d) : "f"(a), "f"(b));
    return d;
}
__device__ __forceinline__ void upk(u64 d, float& a, float& b) {
    asm("mov.b64 {%0, %1}, %2;" : "=f"(a), "=f"(b) : "l"(d));
}
__device__ __forceinline__ void fma2(u64& c, u64 a, u64 b) {
    asm("fma.rn.f32x2 %0, %1, %2, %0;" : "+l"(c) : "l"(a), "l"(b));
}
__device__ __forceinline__ u64 add2(u64 a, u64 b) {
    u64 d;
    asm("add.rn.f32x2 %0, %1, %2;" : "=l"(d) : "l"(a), "l"(b));
    return d;
}

// ---------------------------------------------------------------------------
// Kernel 1: prep — one weight per thread (8 blocks x 128 threads >= 927).
// ---------------------------------------------------------------------------
__global__ void prep_kernel(const float* __restrict__ cw,
                            const float* __restrict__ gam,
                            const float* __restrict__ bet,
                            const float* __restrict__ mu,
                            const float* __restrict__ var) {
    int tid = blockIdx.x * blockDim.x + threadIdx.x;
    if (tid < 675) {
        int k = tid % 9;
        int rest = tid / 9;
        int v = rest % 5; rest /= 5;
        int u = rest % 5;
        int c = rest / 5;
        float s = gam[k] * rsqrtf(var[k] + BN_EPS);
        float sum = 0.f;
#pragma unroll
        for (int ti = 0; ti < 3; ti++) {
            int di = u - ti;
            if (di < 0 || di > 2) continue;
#pragma unroll
            for (int tj = 0; tj < 3; tj++) {
                int dj = v - tj;
                if (dj < 0 || dj > 2) continue;
                int t = ti * 3 + tj;
                if (c == 0 && t >= 4 && t <= 6) continue;   // replaced rows
                sum += cw[((k * 27 + c * 9 + t) * 3 + di) * 3 + dj];
            }
        }
        g_Weff[tid] = s * sum;
    } else if (tid < 675 + 243) {
        int i = tid - 675;
        int k = i % 9;
        int rest = i / 9;
        int v = rest % 3; rest /= 3;
        int u = rest % 3;
        int j = rest / 3;
        float s = gam[k] * rsqrtf(var[k] + BN_EPS);
        g_W0[i] = s * cw[((k * 27 + 4 + j) * 3 + u) * 3 + v];
    } else if (tid < 675 + 243 + 9) {
        int k = tid - 918;
        float s = gam[k] * rsqrtf(var[k] + BN_EPS);
        g_Shift[k] = bet[k] - mu[k] * s;
    }
}

// ---------------------------------------------------------------------------
// Row loader (fast): window [w0-2, w0+5] via LDG.64 + LDG.128 + LDG.64.
// ---------------------------------------------------------------------------
__device__ __forceinline__ void load_row8_fast(const float* __restrict__ p,
                                               float v[8], u64 dup[8]) {
    u64 a = *(const u64*)(p - 2);          // v0,v1
    float4 m = *(const float4*)(p);        // v2..v5 (16B aligned)
    u64 c = *(const u64*)(p + 4);          // v6,v7
    upk(a, v[0], v[1]);
    v[2] = m.x; v[3] = m.y; v[4] = m.z; v[5] = m.w;
    upk(c, v[6], v[7]);
#pragma unroll
    for (int i = 0; i < 8; i++) dup[i] = pk(v[i], v[i]);
}

__device__ __forceinline__ void load_row8_guard(const float* __restrict__ rowp, int w0,
                                                bool rowok, bool colsafe,
                                                float v[8], u64 dup[8]) {
    if (rowok && colsafe) {
        load_row8_fast(rowp + w0, v, dup);
        return;
    }
    if (rowok) {
#pragma unroll
        for (int i = 0; i < 8; i++) {
            int ww = w0 - 2 + i;
            v[i] = (ww >= 0 && ww < W) ? rowp[ww] : 0.f;
        }
    } else {
#pragma unroll
        for (int i = 0; i < 8; i++) v[i] = 0.f;
    }
#pragma unroll
    for (int i = 0; i < 8; i++) dup[i] = pk(v[i], v[i]);
}

// Apply one tap's 9 weights (pairs {w0,w1},{w2,w3},{w4,w5},{w6,w7}, w8 scalar).
__device__ __forceinline__ void apply_tap(const float* __restrict__ wt,
                                          const float v[8], const u64 dup[8], int base,
                                          u64 accp[4][4], float acc8[4]) {
    ulonglong2 qa = *(const ulonglong2*)(wt);
    ulonglong2 qb = *(const ulonglong2*)(wt + 4);
    float w8 = wt[8];
#pragma unroll
    for (int p = 0; p < 4; p++) {
        u64 d = dup[base + p];
        fma2(accp[p][0], qa.x, d);
        fma2(accp[p][1], qa.y, d);
        fma2(accp[p][2], qb.x, d);
        fma2(accp[p][3], qb.y, d);
        acc8[p] = fmaf(w8, v[base + p], acc8[p]);
    }
}

// ---------------------------------------------------------------------------
// Kernel 2: fused main + border.
//   blockIdx.y <  NBY_MAIN : main tile block (8x16 thr, 4 px/thread, 32x16 tile)
//   blockIdx.y >= NBY_MAIN : border block (14 px x 9 didx) for the 1-px ring
// ---------------------------------------------------------------------------
__global__ __launch_bounds__(128, 7) void cspn_main(
        const float* __restrict__ ker,
        const float* __restrict__ in,
        const float* __restrict__ in0,
        const float* __restrict__ cw,
        const float* __restrict__ gam,
        const float* __restrict__ bet,
        const float* __restrict__ mu,
        const float* __restrict__ var,
        float* __restrict__ out) {
    __shared__ __align__(16) char smem_raw[13312];

    const int b = blockIdx.z;
    const int tid = threadIdx.y * 8 + threadIdx.x;

    if (blockIdx.y >= NBY_MAIN) {
        // ================= border path =================
        float* sw   = (float*)smem_raw;                 // [2187]
        float* pacc = (float*)(smem_raw + 8752);        // [BPX][9][9]

        for (int i = tid; i < 2187; i += 128) sw[i] = cw[i];
        __syncthreads();

        const int bidx = (blockIdx.y - NBY_MAIN) * 16 + blockIdx.x;
        const int base = bidx * BPX;

        const int px   = tid / 9;
        const int didx = tid % 9;
        const int pos  = base + px;
        const bool active = (tid < 126) && (pos < RING);

        float acc[9];
#pragma unroll
        for (int k = 0; k < 9; k++) acc[k] = 0.f;

        if (active) {
            int h, w;
            if (pos < W)          { h = 0;     w = pos; }
            else if (pos < 2 * W) { h = H - 1; w = pos - W; }
            else {
                int p2 = pos - 2 * W;
                h = 1 + (p2 >> 1);
                w = (p2 & 1) ? (W - 1) : 0;
            }
            const float* inb  = in  + (size_t)b * 3 * HW;
            const float* in0b = in0 + (size_t)b * 3 * HW;
            const int dy = didx / 3 - 1, dx = didx % 3 - 1;
            const int qy = h + dy, qx = w + dx;
            const bool qok = (qy >= 0 && qy < H && qx >= 0 && qx < W);
#pragma unroll
            for (int ch = 0; ch < 27; ch++) {
                float val;
                if (ch >= 4 && ch <= 6) {
                    val = qok ? in0b[(ch - 4) * HW + qy * W + qx] : 0.f;
                } else {
                    int c = ch / 9, t = ch % 9;
                    int py = qy + t / 3 - 1, qx2 = qx + t % 3 - 1;
                    bool pok = qok && (py >= 0 && py < H && qx2 >= 0 && qx2 < W);
                    val = pok ? inb[c * HW + py * W + qx2] : 0.f;
                }
#pragma unroll
                for (int k = 0; k < 9; k++)
                    acc[k] = fmaf(sw[(k * 27 + ch) * 9 + didx], val, acc[k]);
            }
        }
        if (tid < 126) {
#pragma unroll
            for (int k = 0; k < 9; k++) pacc[(px * 9 + didx) * 9 + k] = acc[k];
        }
        __syncthreads();

        if (tid < BPX) {
            int pos2 = base + tid;
            if (pos2 < RING) {
                int hh, ww;
                if (pos2 < W)          { hh = 0;     ww = pos2; }
                else if (pos2 < 2 * W) { hh = H - 1; ww = pos2 - W; }
                else {
                    int p2 = pos2 - 2 * W;
                    hh = 1 + (p2 >> 1);
                    ww = (p2 & 1) ? (W - 1) : 0;
                }
                float r = 0.f;
#pragma unroll
                for (int k = 0; k < 9; k++) {
                    float s = 0.f;
#pragma unroll
                    for (int d = 0; d < 9; d++) s += pacc[(tid * 9 + d) * 9 + k];
                    float sc = gam[k] * rsqrtf(var[k] + BN_EPS);
                    float sh = bet[k] - mu[k] * sc;
                    r = fmaf(ker[((size_t)b * 9 + k) * HW + hh * W + ww],
                             fmaf(sc, s, sh), r);
                }
                out[(size_t)b * HW + hh * W + ww] = r;
            }
        }
        return;
    }

    // ================= main path =================
    float* sW5 = (float*)smem_raw;                   // [75*12]
    float* s03 = (float*)(smem_raw + 3600);          // [27*12]
    u64*  sSp  = (u64*)(smem_raw + 4896);            // [4]
    float* sS8 = (float*)(smem_raw + 4928);

    for (int i = tid; i < 75 * 12; i += 128) {
        int t5 = i / 12, k = i % 12;
        sW5[i] = (k < 9) ? g_Weff[t5 * 9 + k] : 0.f;
    }
    for (int i = tid; i < 27 * 12; i += 128) {
        int t3 = i / 12, k = i % 12;
        s03[i] = (k < 9) ? g_W0[t3 * 9 + k] : 0.f;
    }
    if (tid < 4) sSp[tid] = pk(g_Shift[2 * tid], g_Shift[2 * tid + 1]);
    if (tid == 4) *sS8 = g_Shift[8];
    __syncthreads();

    const int h  = blockIdx.y * 16 + threadIdx.y;
    const int w0 = blockIdx.x * 32 + threadIdx.x * 4;

    u64 accp[4][4];
    float acc8[4];
#pragma unroll
    for (int p = 0; p < 4; p++) {
        acc8[p] = 0.f;
#pragma unroll
        for (int j = 0; j < 4; j++) accp[p][j] = 0ull;
    }

    const float* inb  = in  + (size_t)b * 3 * HW;
    const float* in0b = in0 + (size_t)b * 3 * HW;

    const bool fast = (blockIdx.x >= 1) && (blockIdx.x <= (W / 32) - 2) &&
                      (blockIdx.y >= 1) && (blockIdx.y <= NBY_MAIN - 2);

    if (fast) {
        const float* base5 = inb + (h - 2) * W + w0;
#pragma unroll
        for (int c = 0; c < 3; c++) {
#pragma unroll
            for (int u = 0; u < 5; u++) {
                float v[8]; u64 dup[8];
                load_row8_fast(base5 + c * HW + u * W, v, dup);
                const float* wrow = &sW5[(c * 5 + u) * 60];
#pragma unroll
                for (int tv = 0; tv < 5; tv++)
                    apply_tap(wrow + tv * 12, v, dup, tv, accp, acc8);
            }
        }
        const float* base3 = in0b + (h - 1) * W + w0;
#pragma unroll
        for (int j3 = 0; j3 < 3; j3++) {
#pragma unroll
            for (int u = 0; u < 3; u++) {
                float v[8]; u64 dup[8];
                load_row8_fast(base3 + j3 * HW + u * W, v, dup);
                const float* wrow = &s03[(j3 * 3 + u) * 36];
#pragma unroll
                for (int tv = 0; tv < 3; tv++)
                    apply_tap(wrow + tv * 12, v, dup, 1 + tv, accp, acc8);
            }
        }
    } else {
        const bool colsafe = (w0 >= 2) && (w0 + 6 <= W);
#pragma unroll 1
        for (int c = 0; c < 3; c++) {
            const float* inc = inb + c * HW;
#pragma unroll 1
            for (int u = 0; u < 5; u++) {
                int r = h + u - 2;
                float v[8]; u64 dup[8];
                load_row8_guard(inc + r * W, w0, (r >= 0 && r < H), colsafe, v, dup);
                const float* wrow = &sW5[(c * 5 + u) * 60];
#pragma unroll
                for (int tv = 0; tv < 5; tv++)
                    apply_tap(wrow + tv * 12, v, dup, tv, accp, acc8);
            }
        }
#pragma unroll 1
        for (int j3 = 0; j3 < 3; j3++) {
            const float* inc = in0b + j3 * HW;
#pragma unroll 1
            for (int u = 0; u < 3; u++) {
                int r = h + u - 1;
                float v[8]; u64 dup[8];
                load_row8_guard(inc + r * W, w0, (r >= 0 && r < H), colsafe, v, dup);
                const float* wrow = &s03[(j3 * 3 + u) * 36];
#pragma unroll
                for (int tv = 0; tv < 3; tv++)
                    apply_tap(wrow + tv * 12, v, dup, 1 + tv, accp, acc8);
            }
        }
    }

    // ---- epilogue ----
    const float* kp = ker + (size_t)b * 9 * HW + h * W + w0;
    u64 rp[4] = {0ull, 0ull, 0ull, 0ull};
#pragma unroll
    for (int j = 0; j < 4; j++) {
        const float4 ka = *(const float4*)(kp + (2 * j) * HW);
        const float4 kb = *(const float4*)(kp + (2 * j + 1) * HW);
        u64 sh2 = sSp[j];
        fma2(rp[0], pk(ka.x, kb.x), add2(accp[0][j], sh2));
        fma2(rp[1], pk(ka.y, kb.y), add2(accp[1][j], sh2));
        fma2(rp[2], pk(ka.z, kb.z), add2(accp[2][j], sh2));
        fma2(rp[3], pk(ka.w, kb.w), add2(accp[3][j], sh2));
    }
    float res[4];
    {
        const float4 k8 = *(const float4*)(kp + 8 * HW);
        float sh8 = *sS8;
        float lo, hi;
        upk(rp[0], lo, hi); res[0] = lo + hi + k8.x * (acc8[0] + sh8);
        upk(rp[1], lo, hi); res[1] = lo + hi + k8.y * (acc8[1] + sh8);
        upk(rp[2], lo, hi); res[2] = lo + hi + k8.z * (acc8[2] + sh8);
        upk(rp[3], lo, hi); res[3] = lo + hi + k8.w * (acc8[3] + sh8);
    }

    // Interior writes only (ring owned by border blocks).
    if (h >= 1 && h <= H - 2) {
        float* op = out + (size_t)b * HW + h * W + w0;
        if (w0 == 0)          { op[1] = res[1]; op[2] = res[2]; op[3] = res[3]; }
        else if (w0 == W - 4) { op[0] = res[0]; op[1] = res[1]; op[2] = res[2]; }
        else                  { *(float4*)op = make_float4(res[0], res[1], res[2], res[3]); }
    }
}

// ---------------------------------------------------------------------------
extern "C" void kernel_launch(void* const* d_in, const int* in_sizes, int n_in,
                              void* d_out, int out_size) {
    const float* ker = (const float*)d_in[0];
    const float* in  = (const float*)d_in[1];
    const float* in0 = (const float*)d_in[2];
    const float* cw  = (const float*)d_in[3];
    const float* gam = (const float*)d_in[4];
    const float* bet = (const float*)d_in[5];
    const float* mu  = (const float*)d_in[6];
    const float* var = (const float*)d_in[7];
    float* out = (float*)d_out;

    int bs = in_sizes[0] / (9 * HW);   // batch from kernel tensor size

    prep_kernel<<<8, 128>>>(cw, gam, bet, mu, var);

    dim3 blk(8, 16);
    dim3 grd(W / 32, NBY_MAIN + NBY_EXTRA, bs);
    cspn_main<<<grd, blk>>>(ker, in, in0, cw, gam, bet, mu, var, out);
}

// round 11
// speedup vs baseline: 1.5169x; 1.2496x over previous
#include <cuda_runtime.h>

#define H 512
#define W 512
#define HW (H * W)
#define BN_EPS 1e-5f
#define RING (4 * W - 4)          // 2044 ring pixels per batch
#define BPX 14                    // border pixels per border block (14*9=126 thr)
#define NBY_MAIN 32               // 512 / 16 rows per main block
#define NBY_EXTRA 10              // 160 border blocks per batch (need 146)

typedef unsigned long long u64;

// Staging (written by prep_kernel) -> copied into __constant__ each launch.
// Layout: [0,900)   5x5 weights, 75 taps x 12 (w0..w8,pad3)
//         [900,1224) 3x3 weights, 27 taps x 12
//         [1224,1232) BN shift pairs (8 floats = 4 u64)
//         [1232]     shift[8]
__device__ float g_stage[1236];
__constant__ __align__(16) float c_all[1236];

// ---------------- packed f32x2 helpers ----------------
__device__ __forceinline__ u64 pk(float a, float b) {
    u64 d;
    asm("mov.b64 %0, {%1, %2};" : "=l"(d) : "f"(a), "f"(b));
    return d;
}
__device__ __forceinline__ void upk(u64 d, float& a, float& b) {
    asm("mov.b64 {%0, %1}, %2;" : "=f"(a), "=f"(b) : "l"(d));
}
__device__ __forceinline__ void fma2(u64& c, u64 a, u64 b) {
    asm("fma.rn.f32x2 %0, %1, %2, %0;" : "+l"(c) : "l"(a), "l"(b));
}
__device__ __forceinline__ u64 add2(u64 a, u64 b) {
    u64 d;
    asm("add.rn.f32x2 %0, %1, %2;" : "=l"(d) : "l"(a), "l"(b));
    return d;
}

// ---------------------------------------------------------------------------
// Kernel 1: prep — one staged entry per thread (10 blocks x 128 >= 1236).
// ---------------------------------------------------------------------------
__global__ void prep_kernel(const float* __restrict__ cw,
                            const float* __restrict__ gam,
                            const float* __restrict__ bet,
                            const float* __restrict__ mu,
                            const float* __restrict__ var) {
    int tid = blockIdx.x * blockDim.x + threadIdx.x;
    if (tid < 900) {
        int t5 = tid / 12, k = tid % 12;
        if (k >= 9) { g_stage[tid] = 0.f; return; }
        int v = t5 % 5, u = (t5 / 5) % 5, c = t5 / 25;
        float s = gam[k] * rsqrtf(var[k] + BN_EPS);
        float sum = 0.f;
#pragma unroll
        for (int ti = 0; ti < 3; ti++) {
            int di = u - ti;
            if (di < 0 || di > 2) continue;
#pragma unroll
            for (int tj = 0; tj < 3; tj++) {
                int dj = v - tj;
                if (dj < 0 || dj > 2) continue;
                int t = ti * 3 + tj;
                if (c == 0 && t >= 4 && t <= 6) continue;   // replaced rows
                sum += cw[((k * 27 + c * 9 + t) * 3 + di) * 3 + dj];
            }
        }
        g_stage[tid] = s * sum;
    } else if (tid < 1224) {
        int i = tid - 900;
        int t3 = i / 12, k = i % 12;
        if (k >= 9) { g_stage[tid] = 0.f; return; }
        int v = t3 % 3, u = (t3 / 3) % 3, j = t3 / 9;
        float s = gam[k] * rsqrtf(var[k] + BN_EPS);
        g_stage[tid] = s * cw[((k * 27 + 4 + j) * 3 + u) * 3 + v];
    } else if (tid < 1233) {
        int k = tid - 1224;     // 0..8
        float s = gam[k] * rsqrtf(var[k] + BN_EPS);
        g_stage[tid] = bet[k] - mu[k] * s;
    } else if (tid < 1236) {
        g_stage[tid] = 0.f;
    }
}

// ---------------------------------------------------------------------------
// Row loader (fast): window [w0-2, w0+5] via LDG.64 + LDG.128 + LDG.64.
// ---------------------------------------------------------------------------
__device__ __forceinline__ void load_row8_fast(const float* __restrict__ p,
                                               float v[8], u64 dup[8]) {
    u64 a = *(const u64*)(p - 2);          // v0,v1
    float4 m = *(const float4*)(p);        // v2..v5 (16B aligned)
    u64 c = *(const u64*)(p + 4);          // v6,v7
    upk(a, v[0], v[1]);
    v[2] = m.x; v[3] = m.y; v[4] = m.z; v[5] = m.w;
    upk(c, v[6], v[7]);
#pragma unroll
    for (int i = 0; i < 8; i++) dup[i] = pk(v[i], v[i]);
}

__device__ __forceinline__ void load_row8_guard(const float* __restrict__ rowp, int w0,
                                                bool rowok, bool colsafe,
                                                float v[8], u64 dup[8]) {
    if (rowok && colsafe) {
        load_row8_fast(rowp + w0, v, dup);
        return;
    }
    if (rowok) {
#pragma unroll
        for (int i = 0; i < 8; i++) {
            int ww = w0 - 2 + i;
            v[i] = (ww >= 0 && ww < W) ? rowp[ww] : 0.f;
        }
    } else {
#pragma unroll
        for (int i = 0; i < 8; i++) v[i] = 0.f;
    }
#pragma unroll
    for (int i = 0; i < 8; i++) dup[i] = pk(v[i], v[i]);
}

// Apply one tap's 9 weights from __constant__ at float-offset woff.
__device__ __forceinline__ void apply_tap_c(int woff,
                                            const float v[8], const u64 dup[8], int base,
                                            u64 accp[4][4], float acc8[4]) {
    ulonglong2 qa = *(const ulonglong2*)&c_all[woff];       // {w0,w1},{w2,w3}
    ulonglong2 qb = *(const ulonglong2*)&c_all[woff + 4];   // {w4,w5},{w6,w7}
    float w8 = c_all[woff + 8];
#pragma unroll
    for (int p = 0; p < 4; p++) {
        u64 d = dup[base + p];
        fma2(accp[p][0], qa.x, d);
        fma2(accp[p][1], qa.y, d);
        fma2(accp[p][2], qb.x, d);
        fma2(accp[p][3], qb.y, d);
        acc8[p] = fmaf(w8, v[base + p], acc8[p]);
    }
}

// ---------------------------------------------------------------------------
// Kernel 2: fused main + border.
//   blockIdx.y <  NBY_MAIN : main tile block (8x16 thr, 4 px/thread)
//   blockIdx.y >= NBY_MAIN : border block (14 px x 9 didx)
// ---------------------------------------------------------------------------
__global__ __launch_bounds__(128, 6) void cspn_main(
        const float* __restrict__ ker,
        const float* __restrict__ in,
        const float* __restrict__ in0,
        const float* __restrict__ cw,
        const float* __restrict__ gam,
        const float* __restrict__ bet,
        const float* __restrict__ mu,
        const float* __restrict__ var,
        float* __restrict__ out) {
    const int b = blockIdx.z;
    const int tid = threadIdx.y * 8 + threadIdx.x;

    if (blockIdx.y >= NBY_MAIN) {
        // ================= border path =================
        __shared__ float sw[2187];
        __shared__ float pacc[BPX * 9 * 9];

        for (int i = tid; i < 2187; i += 128) sw[i] = cw[i];
        __syncthreads();

        const int bidx = (blockIdx.y - NBY_MAIN) * 16 + blockIdx.x;
        const int base = bidx * BPX;

        const int px   = tid / 9;
        const int didx = tid % 9;
        const int pos  = base + px;
        const bool active = (tid < 126) && (pos < RING);

        float acc[9];
#pragma unroll
        for (int k = 0; k < 9; k++) acc[k] = 0.f;

        if (active) {
            int h, w;
            if (pos < W)          { h = 0;     w = pos; }
            else if (pos < 2 * W) { h = H - 1; w = pos - W; }
            else {
                int p2 = pos - 2 * W;
                h = 1 + (p2 >> 1);
                w = (p2 & 1) ? (W - 1) : 0;
            }
            const float* inb  = in  + (size_t)b * 3 * HW;
            const float* in0b = in0 + (size_t)b * 3 * HW;
            const int dy = didx / 3 - 1, dx = didx % 3 - 1;
            const int qy = h + dy, qx = w + dx;
            const bool qok = (qy >= 0 && qy < H && qx >= 0 && qx < W);
#pragma unroll
            for (int ch = 0; ch < 27; ch++) {
                float val;
                if (ch >= 4 && ch <= 6) {
                    val = qok ? in0b[(ch - 4) * HW + qy * W + qx] : 0.f;
                } else {
                    int c = ch / 9, t = ch % 9;
                    int py = qy + t / 3 - 1, qx2 = qx + t % 3 - 1;
                    bool pok = qok && (py >= 0 && py < H && qx2 >= 0 && qx2 < W);
                    val = pok ? inb[c * HW + py * W + qx2] : 0.f;
                }
#pragma unroll
                for (int k = 0; k < 9; k++)
                    acc[k] = fmaf(sw[(k * 27 + ch) * 9 + didx], val, acc[k]);
            }
        }
        if (tid < 126) {
#pragma unroll
            for (int k = 0; k < 9; k++) pacc[(px * 9 + didx) * 9 + k] = acc[k];
        }
        __syncthreads();

        if (tid < BPX) {
            int pos2 = base + tid;
            if (pos2 < RING) {
                int hh, ww;
                if (pos2 < W)          { hh = 0;     ww = pos2; }
                else if (pos2 < 2 * W) { hh = H - 1; ww = pos2 - W; }
                else {
                    int p2 = pos2 - 2 * W;
                    hh = 1 + (p2 >> 1);
                    ww = (p2 & 1) ? (W - 1) : 0;
                }
                float r = 0.f;
#pragma unroll
                for (int k = 0; k < 9; k++) {
                    float s = 0.f;
#pragma unroll
                    for (int d = 0; d < 9; d++) s += pacc[(tid * 9 + d) * 9 + k];
                    float sc = gam[k] * rsqrtf(var[k] + BN_EPS);
                    float sh = bet[k] - mu[k] * sc;
                    r = fmaf(ker[((size_t)b * 9 + k) * HW + hh * W + ww],
                             fmaf(sc, s, sh), r);
                }
                out[(size_t)b * HW + hh * W + ww] = r;
            }
        }
        return;
    }

    // ================= main path (weights from __constant__) =================
    const int h  = blockIdx.y * 16 + threadIdx.y;
    const int w0 = blockIdx.x * 32 + threadIdx.x * 4;

    u64 accp[4][4];
    float acc8[4];
#pragma unroll
    for (int p = 0; p < 4; p++) {
        acc8[p] = 0.f;
#pragma unroll
        for (int j = 0; j < 4; j++) accp[p][j] = 0ull;
    }

    const float* inb  = in  + (size_t)b * 3 * HW;
    const float* in0b = in0 + (size_t)b * 3 * HW;

    const bool fast = (blockIdx.x >= 1) && (blockIdx.x <= (W / 32) - 2) &&
                      (blockIdx.y >= 1) && (blockIdx.y <= NBY_MAIN - 2);

    if (fast) {
        const float* base5 = inb + (h - 2) * W + w0;
#pragma unroll
        for (int c = 0; c < 3; c++) {
#pragma unroll
            for (int u = 0; u < 5; u++) {
                float v[8]; u64 dup[8];
                load_row8_fast(base5 + c * HW + u * W, v, dup);
#pragma unroll
                for (int tv = 0; tv < 5; tv++)
                    apply_tap_c(((c * 5 + u) * 5 + tv) * 12, v, dup, tv, accp, acc8);
            }
        }
        const float* base3 = in0b + (h - 1) * W + w0;
#pragma unroll
        for (int j3 = 0; j3 < 3; j3++) {
#pragma unroll
            for (int u = 0; u < 3; u++) {
                float v[8]; u64 dup[8];
                load_row8_fast(base3 + j3 * HW + u * W, v, dup);
#pragma unroll
                for (int tv = 0; tv < 3; tv++)
                    apply_tap_c(900 + ((j3 * 3 + u) * 3 + tv) * 12, v, dup, 1 + tv, accp, acc8);
            }
        }
    } else {
        const bool colsafe = (w0 >= 2) && (w0 + 6 <= W);
#pragma unroll 1
        for (int c = 0; c < 3; c++) {
            const float* inc = inb + c * HW;
#pragma unroll 1
            for (int u = 0; u < 5; u++) {
                int r = h + u - 2;
                float v[8]; u64 dup[8];
                load_row8_guard(inc + r * W, w0, (r >= 0 && r < H), colsafe, v, dup);
#pragma unroll
                for (int tv = 0; tv < 5; tv++)
                    apply_tap_c(((c * 5 + u) * 5 + tv) * 12, v, dup, tv, accp, acc8);
            }
        }
#pragma unroll 1
        for (int j3 = 0; j3 < 3; j3++) {
            const float* inc = in0b + j3 * HW;
#pragma unroll 1
            for (int u = 0; u < 3; u++) {
                int r = h + u - 1;
                float v[8]; u64 dup[8];
                load_row8_guard(inc + r * W, w0, (r >= 0 && r < H), colsafe, v, dup);
#pragma unroll
                for (int tv = 0; tv < 3; tv++)
                    apply_tap_c(900 + ((j3 * 3 + u) * 3 + tv) * 12, v, dup, 1 + tv, accp, acc8);
            }
        }
    }

    // ---- epilogue ----
    const float* kp = ker + (size_t)b * 9 * HW + h * W + w0;
    u64 rp[4] = {0ull, 0ull, 0ull, 0ull};
#pragma unroll
    for (int j = 0; j < 4; j++) {
        const float4 ka = *(const float4*)(kp + (2 * j) * HW);
        const float4 kb = *(const float4*)(kp + (2 * j + 1) * HW);
        u64 sh2 = *(const u64*)&c_all[1224 + 2 * j];
        fma2(rp[0], pk(ka.x, kb.x), add2(accp[0][j], sh2));
        fma2(rp[1], pk(ka.y, kb.y), add2(accp[1][j], sh2));
        fma2(rp[2], pk(ka.z, kb.z), add2(accp[2][j], sh2));
        fma2(rp[3], pk(ka.w, kb.w), add2(accp[3][j], sh2));
    }
    float res[4];
    {
        const float4 k8 = *(const float4*)(kp + 8 * HW);
        float sh8 = c_all[1232];
        float lo, hi;
        upk(rp[0], lo, hi); res[0] = lo + hi + k8.x * (acc8[0] + sh8);
        upk(rp[1], lo, hi); res[1] = lo + hi + k8.y * (acc8[1] + sh8);
        upk(rp[2], lo, hi); res[2] = lo + hi + k8.z * (acc8[2] + sh8);
        upk(rp[3], lo, hi); res[3] = lo + hi + k8.w * (acc8[3] + sh8);
    }

    // Interior writes only (ring owned by border blocks).
    if (h >= 1 && h <= H - 2) {
        float* op = out + (size_t)b * HW + h * W + w0;
        if (w0 == 0)          { op[1] = res[1]; op[2] = res[2]; op[3] = res[3]; }
        else if (w0 == W - 4) { op[0] = res[0]; op[1] = res[1]; op[2] = res[2]; }
        else                  { *(float4*)op = make_float4(res[0], res[1], res[2], res[3]); }
    }
}

// ---------------------------------------------------------------------------
extern "C" void kernel_launch(void* const* d_in, const int* in_sizes, int n_in,
                              void* d_out, int out_size) {
    const float* ker = (const float*)d_in[0];
    const float* in  = (const float*)d_in[1];
    const float* in0 = (const float*)d_in[2];
    const float* cw  = (const float*)d_in[3];
    const float* gam = (const float*)d_in[4];
    const float* bet = (const float*)d_in[5];
    const float* mu  = (const float*)d_in[6];
    const float* var = (const float*)d_in[7];
    float* out = (float*)d_out;

    int bs = in_sizes[0] / (9 * HW);   // batch from kernel tensor size

    prep_kernel<<<10, 128>>>(cw, gam, bet, mu, var);

    // Async D2D copy staged weights into __constant__ (graph-capturable).
    void* stage_ptr = nullptr;
    cudaGetSymbolAddress(&stage_ptr, g_stage);
    cudaMemcpyToSymbolAsync(c_all, stage_ptr, 1236 * sizeof(float), 0,
                            cudaMemcpyDeviceToDevice);

    dim3 blk(8, 16);
    dim3 grd(W / 32, NBY_MAIN + NBY_EXTRA, bs);
    cspn_main<<<grd, blk>>>(ker, in, in0, cw, gam, bet, mu, var, out);
}

// round 12
// speedup vs baseline: 1.5322x; 1.0100x over previous
#include <cuda_runtime.h>

#define H 512
#define W 512
#define HW (H * W)
#define BN_EPS 1e-5f
#define RING (4 * W - 4)          // 2044 ring pixels per batch
#define BPX 14                    // border pixels per border block (14*9=126 thr)
#define NBY_MAIN 32               // 512 / 16 rows per main block
#define NBY_EXTRA 10              // 160 border blocks per batch (need 146)

typedef unsigned long long u64;

// Staging (written by prep_kernel) -> copied into __constant__ each launch.
// Layout per tap (12 floats): w0..w7, w8, w8, 0, 0   (slot9 = dup of w8)
//   [0,900)    5x5 weights, 75 taps x 12
//   [900,1224) 3x3 weights, 27 taps x 12
//   [1224,1232) BN shift pairs (8 floats = 4 u64)
//   [1232]     shift[8]
__device__ float g_stage[1236];
__constant__ __align__(16) float c_all[1236];

// ---------------- packed f32x2 helpers ----------------
__device__ __forceinline__ u64 pk(float a, float b) {
    u64 d;
    asm("mov.b64 %0, {%1, %2};" : "=l"(d) : "f"(a), "f"(b));
    return d;
}
__device__ __forceinline__ void upk(u64 d, float& a, float& b) {
    asm("mov.b64 {%0, %1}, %2;" : "=f"(a), "=f"(b) : "l"(d));
}
__device__ __forceinline__ void fma2(u64& c, u64 a, u64 b) {
    asm("fma.rn.f32x2 %0, %1, %2, %0;" : "+l"(c) : "l"(a), "l"(b));
}
__device__ __forceinline__ u64 add2(u64 a, u64 b) {
    u64 d;
    asm("add.rn.f32x2 %0, %1, %2;" : "=l"(d) : "l"(a), "l"(b));
    return d;
}

// ---------------------------------------------------------------------------
// Kernel 1: prep — one staged entry per thread (10 blocks x 128 >= 1236).
// ---------------------------------------------------------------------------
__global__ void prep_kernel(const float* __restrict__ cw,
                            const float* __restrict__ gam,
                            const float* __restrict__ bet,
                            const float* __restrict__ mu,
                            const float* __restrict__ var) {
    int tid = blockIdx.x * blockDim.x + threadIdx.x;
    if (tid < 900) {
        int t5 = tid / 12, kk = tid % 12;
        if (kk >= 10) { g_stage[tid] = 0.f; return; }
        int k = (kk == 9) ? 8 : kk;             // slot 9 duplicates w8
        int v = t5 % 5, u = (t5 / 5) % 5, c = t5 / 25;
        float s = gam[k] * rsqrtf(var[k] + BN_EPS);
        float sum = 0.f;
#pragma unroll
        for (int ti = 0; ti < 3; ti++) {
            int di = u - ti;
            if (di < 0 || di > 2) continue;
#pragma unroll
            for (int tj = 0; tj < 3; tj++) {
                int dj = v - tj;
                if (dj < 0 || dj > 2) continue;
                int t = ti * 3 + tj;
                if (c == 0 && t >= 4 && t <= 6) continue;   // replaced rows
                sum += cw[((k * 27 + c * 9 + t) * 3 + di) * 3 + dj];
            }
        }
        g_stage[tid] = s * sum;
    } else if (tid < 1224) {
        int i = tid - 900;
        int t3 = i / 12, kk = i % 12;
        if (kk >= 10) { g_stage[tid] = 0.f; return; }
        int k = (kk == 9) ? 8 : kk;
        int v = t3 % 3, u = (t3 / 3) % 3, j = t3 / 9;
        float s = gam[k] * rsqrtf(var[k] + BN_EPS);
        g_stage[tid] = s * cw[((k * 27 + 4 + j) * 3 + u) * 3 + v];
    } else if (tid < 1233) {
        int k = tid - 1224;     // 0..8
        float s = gam[k] * rsqrtf(var[k] + BN_EPS);
        g_stage[tid] = bet[k] - mu[k] * s;
    } else if (tid < 1236) {
        g_stage[tid] = 0.f;
    }
}

// ---------------------------------------------------------------------------
// Row loaders over window [w0-2, w0+5].
//   dup[i] = {v[i], v[i]}   (broadcast data, for k0..7 packed weight pairs)
//   adj[i] = {v[i], v[i+1]} (adjacent-pixel pairs, for packed k8)
// ---------------------------------------------------------------------------
__device__ __forceinline__ void build_pairs(const float v[8], u64 dup[8], u64 adj[7]) {
#pragma unroll
    for (int i = 0; i < 8; i++) dup[i] = pk(v[i], v[i]);
#pragma unroll
    for (int i = 0; i < 7; i++) adj[i] = pk(v[i], v[i + 1]);
}

__device__ __forceinline__ void load_row8_fast(const float* __restrict__ p,
                                               u64 dup[8], u64 adj[7]) {
    float v[8];
    u64 a = *(const u64*)(p - 2);          // v0,v1
    float4 m = *(const float4*)(p);        // v2..v5 (16B aligned)
    u64 c = *(const u64*)(p + 4);          // v6,v7
    upk(a, v[0], v[1]);
    v[2] = m.x; v[3] = m.y; v[4] = m.z; v[5] = m.w;
    upk(c, v[6], v[7]);
    build_pairs(v, dup, adj);
}

__device__ __forceinline__ void load_row8_guard(const float* __restrict__ rowp, int w0,
                                                bool rowok, bool colsafe,
                                                u64 dup[8], u64 adj[7]) {
    if (rowok && colsafe) {
        load_row8_fast(rowp + w0, dup, adj);
        return;
    }
    float v[8];
    if (rowok) {
#pragma unroll
        for (int i = 0; i < 8; i++) {
            int ww = w0 - 2 + i;
            v[i] = (ww >= 0 && ww < W) ? rowp[ww] : 0.f;
        }
    } else {
#pragma unroll
        for (int i = 0; i < 8; i++) v[i] = 0.f;
    }
    build_pairs(v, dup, adj);
}

// Apply one tap's 9 weights from __constant__ at float-offset woff.
// k0..7: packed weight pairs x broadcast data; k8: dup'd weight x pixel pairs.
__device__ __forceinline__ void apply_tap_c(int woff,
                                            const u64 dup[8], const u64 adj[7], int base,
                                            u64 accp[4][4], u64 acc8p[2]) {
    ulonglong2 qa = *(const ulonglong2*)&c_all[woff];       // {w0,w1},{w2,w3}
    ulonglong2 qb = *(const ulonglong2*)&c_all[woff + 4];   // {w4,w5},{w6,w7}
    u64 w8d = *(const u64*)&c_all[woff + 8];                // {w8,w8}
#pragma unroll
    for (int p = 0; p < 4; p++) {
        u64 d = dup[base + p];
        fma2(accp[p][0], qa.x, d);
        fma2(accp[p][1], qa.y, d);
        fma2(accp[p][2], qb.x, d);
        fma2(accp[p][3], qb.y, d);
    }
    fma2(acc8p[0], w8d, adj[base]);       // pixels (0,1)
    fma2(acc8p[1], w8d, adj[base + 2]);   // pixels (2,3)
}

// ---------------------------------------------------------------------------
// Kernel 2: fused main + border.
// ---------------------------------------------------------------------------
__global__ __launch_bounds__(128, 6) void cspn_main(
        const float* __restrict__ ker,
        const float* __restrict__ in,
        const float* __restrict__ in0,
        const float* __restrict__ cw,
        const float* __restrict__ gam,
        const float* __restrict__ bet,
        const float* __restrict__ mu,
        const float* __restrict__ var,
        float* __restrict__ out) {
    const int b = blockIdx.z;
    const int tid = threadIdx.y * 8 + threadIdx.x;

    if (blockIdx.y >= NBY_MAIN) {
        // ================= border path =================
        __shared__ float sw[2187];
        __shared__ float pacc[BPX * 9 * 9];

        for (int i = tid; i < 2187; i += 128) sw[i] = cw[i];
        __syncthreads();

        const int bidx = (blockIdx.y - NBY_MAIN) * 16 + blockIdx.x;
        const int base = bidx * BPX;

        const int px   = tid / 9;
        const int didx = tid % 9;
        const int pos  = base + px;
        const bool active = (tid < 126) && (pos < RING);

        float acc[9];
#pragma unroll
        for (int k = 0; k < 9; k++) acc[k] = 0.f;

        if (active) {
            int h, w;
            if (pos < W)          { h = 0;     w = pos; }
            else if (pos < 2 * W) { h = H - 1; w = pos - W; }
            else {
                int p2 = pos - 2 * W;
                h = 1 + (p2 >> 1);
                w = (p2 & 1) ? (W - 1) : 0;
            }
            const float* inb  = in  + (size_t)b * 3 * HW;
            const float* in0b = in0 + (size_t)b * 3 * HW;
            const int dy = didx / 3 - 1, dx = didx % 3 - 1;
            const int qy = h + dy, qx = w + dx;
            const bool qok = (qy >= 0 && qy < H && qx >= 0 && qx < W);
#pragma unroll
            for (int ch = 0; ch < 27; ch++) {
                float val;
                if (ch >= 4 && ch <= 6) {
                    val = qok ? in0b[(ch - 4) * HW + qy * W + qx] : 0.f;
                } else {
                    int c = ch / 9, t = ch % 9;
                    int py = qy + t / 3 - 1, qx2 = qx + t % 3 - 1;
                    bool pok = qok && (py >= 0 && py < H && qx2 >= 0 && qx2 < W);
                    val = pok ? inb[c * HW + py * W + qx2] : 0.f;
                }
#pragma unroll
                for (int k = 0; k < 9; k++)
                    acc[k] = fmaf(sw[(k * 27 + ch) * 9 + didx], val, acc[k]);
            }
        }
        if (tid < 126) {
#pragma unroll
            for (int k = 0; k < 9; k++) pacc[(px * 9 + didx) * 9 + k] = acc[k];
        }
        __syncthreads();

        if (tid < BPX) {
            int pos2 = base + tid;
            if (pos2 < RING) {
                int hh, ww;
                if (pos2 < W)          { hh = 0;     ww = pos2; }
                else if (pos2 < 2 * W) { hh = H - 1; ww = pos2 - W; }
                else {
                    int p2 = pos2 - 2 * W;
                    hh = 1 + (p2 >> 1);
                    ww = (p2 & 1) ? (W - 1) : 0;
                }
                float r = 0.f;
#pragma unroll
                for (int k = 0; k < 9; k++) {
                    float s = 0.f;
#pragma unroll
                    for (int d = 0; d < 9; d++) s += pacc[(tid * 9 + d) * 9 + k];
                    float sc = gam[k] * rsqrtf(var[k] + BN_EPS);
                    float sh = bet[k] - mu[k] * sc;
                    r = fmaf(ker[((size_t)b * 9 + k) * HW + hh * W + ww],
                             fmaf(sc, s, sh), r);
                }
                out[(size_t)b * HW + hh * W + ww] = r;
            }
        }
        return;
    }

    // ================= main path (weights from __constant__) =================
    const int h  = blockIdx.y * 16 + threadIdx.y;
    const int w0 = blockIdx.x * 32 + threadIdx.x * 4;

    u64 accp[4][4];
    u64 acc8p[2] = {0ull, 0ull};
#pragma unroll
    for (int p = 0; p < 4; p++)
#pragma unroll
        for (int j = 0; j < 4; j++) accp[p][j] = 0ull;

    const float* inb  = in  + (size_t)b * 3 * HW;
    const float* in0b = in0 + (size_t)b * 3 * HW;

    const bool fast = (blockIdx.x >= 1) && (blockIdx.x <= (W / 32) - 2) &&
                      (blockIdx.y >= 1) && (blockIdx.y <= NBY_MAIN - 2);

    if (fast) {
        const float* base5 = inb + (h - 2) * W + w0;
#pragma unroll
        for (int c = 0; c < 3; c++) {
#pragma unroll
            for (int u = 0; u < 5; u++) {
                u64 dup[8], adj[7];
                load_row8_fast(base5 + c * HW + u * W, dup, adj);
#pragma unroll
                for (int tv = 0; tv < 5; tv++)
                    apply_tap_c(((c * 5 + u) * 5 + tv) * 12, dup, adj, tv, accp, acc8p);
            }
        }
        const float* base3 = in0b + (h - 1) * W + w0;
#pragma unroll
        for (int j3 = 0; j3 < 3; j3++) {
#pragma unroll
            for (int u = 0; u < 3; u++) {
                u64 dup[8], adj[7];
                load_row8_fast(base3 + j3 * HW + u * W, dup, adj);
#pragma unroll
                for (int tv = 0; tv < 3; tv++)
                    apply_tap_c(900 + ((j3 * 3 + u) * 3 + tv) * 12, dup, adj, 1 + tv, accp, acc8p);
            }
        }
    } else {
        const bool colsafe = (w0 >= 2) && (w0 + 6 <= W);
#pragma unroll 1
        for (int c = 0; c < 3; c++) {
            const float* inc = inb + c * HW;
#pragma unroll 1
            for (int u = 0; u < 5; u++) {
                int r = h + u - 2;
                u64 dup[8], adj[7];
                load_row8_guard(inc + r * W, w0, (r >= 0 && r < H), colsafe, dup, adj);
#pragma unroll
                for (int tv = 0; tv < 5; tv++)
                    apply_tap_c(((c * 5 + u) * 5 + tv) * 12, dup, adj, tv, accp, acc8p);
            }
        }
#pragma unroll 1
        for (int j3 = 0; j3 < 3; j3++) {
            const float* inc = in0b + j3 * HW;
#pragma unroll 1
            for (int u = 0; u < 3; u++) {
                int r = h + u - 1;
                u64 dup[8], adj[7];
                load_row8_guard(inc + r * W, w0, (r >= 0 && r < H), colsafe, dup, adj);
#pragma unroll
                for (int tv = 0; tv < 3; tv++)
                    apply_tap_c(900 + ((j3 * 3 + u) * 3 + tv) * 12, dup, adj, 1 + tv, accp, acc8p);
            }
        }
    }

    // ---- epilogue ----
    const float* kp = ker + (size_t)b * 9 * HW + h * W + w0;
    u64 rp[4] = {0ull, 0ull, 0ull, 0ull};
#pragma unroll
    for (int j = 0; j < 4; j++) {
        const float4 ka = *(const float4*)(kp + (2 * j) * HW);
        const float4 kb = *(const float4*)(kp + (2 * j + 1) * HW);
        u64 sh2 = *(const u64*)&c_all[1224 + 2 * j];
        fma2(rp[0], pk(ka.x, kb.x), add2(accp[0][j], sh2));
        fma2(rp[1], pk(ka.y, kb.y), add2(accp[1][j], sh2));
        fma2(rp[2], pk(ka.z, kb.z), add2(accp[2][j], sh2));
        fma2(rp[3], pk(ka.w, kb.w), add2(accp[3][j], sh2));
    }
    float res[4];
    {
        const float4 k8 = *(const float4*)(kp + 8 * HW);
        float sh8 = c_all[1232];
        float a80, a81, a82, a83;
        upk(acc8p[0], a80, a81);
        upk(acc8p[1], a82, a83);
        float lo, hi;
        upk(rp[0], lo, hi); res[0] = lo + hi + k8.x * (a80 + sh8);
        upk(rp[1], lo, hi); res[1] = lo + hi + k8.y * (a81 + sh8);
        upk(rp[2], lo, hi); res[2] = lo + hi + k8.z * (a82 + sh8);
        upk(rp[3], lo, hi); res[3] = lo + hi + k8.w * (a83 + sh8);
    }

    // Interior writes only (ring owned by border blocks).
    if (h >= 1 && h <= H - 2) {
        float* op = out + (size_t)b * HW + h * W + w0;
        if (w0 == 0)          { op[1] = res[1]; op[2] = res[2]; op[3] = res[3]; }
        else if (w0 == W - 4) { op[0] = res[0]; op[1] = res[1]; op[2] = res[2]; }
        else                  { *(float4*)op = make_float4(res[0], res[1], res[2], res[3]); }
    }
}

// ---------------------------------------------------------------------------
extern "C" void kernel_launch(void* const* d_in, const int* in_sizes, int n_in,
                              void* d_out, int out_size) {
    const float* ker = (const float*)d_in[0];
    const float* in  = (const float*)d_in[1];
    const float* in0 = (const float*)d_in[2];
    const float* cw  = (const float*)d_in[3];
    const float* gam = (const float*)d_in[4];
    const float* bet = (const float*)d_in[5];
    const float* mu  = (const float*)d_in[6];
    const float* var = (const float*)d_in[7];
    float* out = (float*)d_out;

    int bs = in_sizes[0] / (9 * HW);   // batch from kernel tensor size

    prep_kernel<<<10, 128>>>(cw, gam, bet, mu, var);

    // Async D2D copy staged weights into __constant__ (graph-capturable).
    void* stage_ptr = nullptr;
    cudaGetSymbolAddress(&stage_ptr, g_stage);
    cudaMemcpyToSymbolAsync(c_all, stage_ptr, 1236 * sizeof(float), 0,
                            cudaMemcpyDeviceToDevice);

    dim3 blk(8, 16);
    dim3 grd(W / 32, NBY_MAIN + NBY_EXTRA, bs);
    cspn_main<<<grd, blk>>>(ker, in, in0, cw, gam, bet, mu, var, out);
}